// round 2
// baseline (speedup 1.0000x reference)
#include <cuda_runtime.h>
#include <cuda_bf16.h>

// Fan-beam CT forward projector, gather formulation.
#define IMG_R 384
#define IMG_C 384
#define N_COLS 768
#define N_VIEWS 256
#define DR_F 1.0f
#define DC_F 1.0f
#define DSPACE_F 1.5f

__global__ __launch_bounds__(256)
void fanbeam_gather_kernel(
    const float* __restrict__ img,      // (R, C)
    const float* __restrict__ src_a,    // (V, 1, 2)
    const float* __restrict__ detc_a,   // (V, 1, 2)
    const float* __restrict__ u_a,      // (V, 1, 2)
    const float* __restrict__ center_a, // (2,)
    const float* __restrict__ cdir_a,   // (2,)
    float* __restrict__ out)            // (V, N_COLS)
{
    const int v = blockIdx.y;
    const int j = blockIdx.x * blockDim.x + threadIdx.x;   // detector column

    // ---- per-view geometry ----
    const float sx  = src_a[2 * v],  sy  = src_a[2 * v + 1];
    const float dcx = detc_a[2 * v], dcy = detc_a[2 * v + 1];
    const float ux  = u_a[2 * v],    uy  = u_a[2 * v + 1];
    const float cx  = center_a[0],   cy  = center_a[1];
    const float cdx = cdir_a[0],     cdy = cdir_a[1];

    const float rdx = -cdy, rdy = cdx;                      // row direction
    const float vzx = cx - 0.5f * (IMG_R - 1) * DR_F * rdx - 0.5f * (IMG_C - 1) * DC_F * cdx;
    const float vzy = cy - 0.5f * (IMG_R - 1) * DR_F * rdy - 0.5f * (IMG_C - 1) * DC_F * cdy;

    const float nx = -uy, ny = ux;                          // detector normal
    const float ref_d = dcx * nx + dcy * ny;
    const float src_d = sx * nx + sy * ny;
    const float nu    = ref_d - src_d;                      // t numerator (const/view)
    const float src_u = sx * ux + sy * uy;
    const float uu    = ux * ux + uy * uy;
    const float zero_u = (dcx * ux + dcy * uy) - 0.5f * (N_COLS - 1) * DSPACE_F * uu;
    const float su0   = src_u - zero_u;

    // den(r,c) = P.n - src_d = dn00 + r*dnr + c*dnc ; pu(r,c) = P.u - src_u similarly
    const float dn00 = vzx * nx + vzy * ny - src_d;
    const float dnr  = (rdx * nx + rdy * ny) * DR_F;
    const float dnc  = (cdx * nx + cdy * ny) * DC_F;
    const float pu00 = vzx * ux + vzy * uy - src_u;
    const float pur  = (rdx * ux + rdy * uy) * DR_F;
    const float puc  = (cdx * ux + cdy * uy) * DC_F;

    // col(c) = (A(r) + B*c) / (DSPACE * den(r,c)),  den > 0 in this geometry.
    //   A(r) = su0*dn0(r) + nu*pu0(r),  B = su0*dnc + nu*puc  (const per view)
    // Window as linear inequalities (no pole issues):
    //   col > j-1  <=>  (A - jmD*dn0) + c*(B - jmD*dnc) > 0
    //   col < j+1  <=>  (A - jpD*dn0) + c*(B - jpD*dnc) < 0
    // Each is a lower OR upper bound on c depending on sign(beta); beta is
    // per-thread constant, so the direction choice hoists out of the row loop.
    const float Bc  = su0 * dnc + nu * puc;
    const float jf  = (float)j;
    const float jmD = (jf - 1.0f) * DSPACE_F;
    const float jpD = (jf + 1.0f) * DSPACE_F;
    const float bm  = Bc - jmD * dnc;
    const float bp  = Bc - jpD * dnc;
    const float rBm = __frcp_rn(bm);
    const float rBp = __frcp_rn(bp);
    const bool  m_lower = (bm > 0.0f);   // beta_m > 0 -> c > cm (lower bound)
    const bool  p_lower = (bp < 0.0f);   // beta_p < 0 -> c > cp (lower bound)
    const float invD = 1.0f / DSPACE_F;

    float acc = 0.0f;

    for (int r = 0; r < IMG_R; ++r) {
        const float rf  = (float)r;
        const float dn0 = fmaf(rf, dnr, dn00);
        const float pu0 = fmaf(rf, pur, pu00);
        const float A   = fmaf(su0, dn0, nu * pu0);

        float lo = 0.0f;
        float hi = (float)(IMG_C - 1);
        const float cm = fmaf(jmD, dn0, -A) * rBm;  // inverse at q = j-1
        const float cp = fmaf(jpD, dn0, -A) * rBp;  // inverse at q = j+1
        if (m_lower) lo = fmaxf(lo, cm); else hi = fminf(hi, cm);
        if (p_lower) lo = fmaxf(lo, cp); else hi = fminf(hi, cp);
        if (hi < lo) continue;                      // window outside image

        int ilo = (int)lo - 1; if (ilo < 0) ilo = 0;
        int ihi = (int)hi + 2; if (ihi > IMG_C - 1) ihi = IMG_C - 1;

        const float* row = img + r * IMG_C;
        for (int c = ilo; c <= ihi; ++c) {
            const float cf  = (float)c;
            const float den = fmaf(cf, dnc, dn0);            // P.n - src_d
            const float pu  = fmaf(cf, puc, pu0);            // P.u - src_u
            const float t   = __fdividef(nu, den);
            const float col = fmaf(t, pu, su0) * invD;
            const float w   = 1.0f - fabsf(col - jf);
            if (w > 0.0f && t > 0.0f)
                acc = fmaf(w, row[c], acc);
        }
    }

    out[v * N_COLS + j] = acc;
}

extern "C" void kernel_launch(void* const* d_in, const int* in_sizes, int n_in,
                              void* d_out, int out_size) {
    const float* img    = (const float*)d_in[0];
    const float* src    = (const float*)d_in[1];
    const float* detc   = (const float*)d_in[2];
    const float* u      = (const float*)d_in[3];
    const float* center = (const float*)d_in[4];
    const float* cdir   = (const float*)d_in[5];
    float* out = (float*)d_out;

    dim3 grid(N_COLS / 256, N_VIEWS);
    fanbeam_gather_kernel<<<grid, 256>>>(img, src, detc, u, center, cdir, out);
}

// round 3
// speedup vs baseline: 3.2236x; 3.2236x over previous
#include <cuda_runtime.h>
#include <cuda_bf16.h>

#define IMG_R 384
#define IMG_C 384
#define N_COLS 768
#define N_VIEWS 256
#define DSPACE_F 1.5f

__global__ __launch_bounds__(256)
void fanbeam_gather_kernel(
    const float* __restrict__ img,      // (R, C)
    const float* __restrict__ src_a,    // (V, 1, 2)
    const float* __restrict__ detc_a,   // (V, 1, 2)
    const float* __restrict__ u_a,      // (V, 1, 2)
    const float* __restrict__ center_a, // (2,)
    const float* __restrict__ cdir_a,   // (2,)
    float* __restrict__ out)            // (V, N_COLS)
{
    const int v    = blockIdx.y;
    const int lane = threadIdx.x & 31;
    const int warp = threadIdx.x >> 5;
    // load-balance remap: each block mixes detector chunks across the fan
    const int chunk = warp * 3 + blockIdx.x;      // 0..23
    const int j     = (chunk << 5) | lane;        // detector column

    // ---- per-view geometry ----
    const float sx  = src_a[2 * v],  sy  = src_a[2 * v + 1];
    const float dcx = detc_a[2 * v], dcy = detc_a[2 * v + 1];
    const float ux  = u_a[2 * v],    uy  = u_a[2 * v + 1];
    const float cx  = center_a[0],   cy  = center_a[1];
    const float cdx = cdir_a[0],     cdy = cdir_a[1];

    const float rdx = -cdy, rdy = cdx;
    const float vzx = cx - 0.5f * (IMG_R - 1) * rdx - 0.5f * (IMG_C - 1) * cdx;
    const float vzy = cy - 0.5f * (IMG_R - 1) * rdy - 0.5f * (IMG_C - 1) * cdy;

    const float nx = -uy, ny = ux;
    const float ref_d = dcx * nx + dcy * ny;
    const float src_d = sx * nx + sy * ny;
    const float nu    = ref_d - src_d;                      // t numerator, >0 here
    const float src_u = sx * ux + sy * uy;
    const float uu    = ux * ux + uy * uy;
    const float zero_u = (dcx * ux + dcy * uy) - 0.5f * (N_COLS - 1) * DSPACE_F * uu;
    const float invD  = 1.0f / DSPACE_F;
    const float su0D  = (src_u - zero_u) * invD;            // pre-scaled by 1/DSPACE

    const float dn00 = vzx * nx + vzy * ny - src_d;
    const float dnr  = rdx * nx + rdy * ny;
    const float dnc  = cdx * nx + cdy * ny;
    const float pu00D = (vzx * ux + vzy * uy - src_u) * invD;
    const float purD  = (rdx * ux + rdy * uy) * invD;
    const float pucD  = (cdx * ux + cdy * uy) * invD;

    // col(r,c)*den(r,c) = A(r) + B*c ;  den(r,c) = dn0(r) + c*dnc > 0
    const float A0 = su0D * dn00 + nu * pu00D;
    const float Ar = su0D * dnr  + nu * purD;
    const float Bc = su0D * dnc  + nu * pucD;

    // shared per-row view constants (same for all threads of the block)
    __shared__ float sh_dn0[IMG_R], sh_AD[IMG_R], sh_pu0[IMG_R];
    for (int i = threadIdx.x; i < IMG_R; i += 256) {
        const float rf = (float)i;
        sh_dn0[i] = fmaf(rf, dnr,   dn00);
        sh_AD[i]  = fmaf(rf, Ar,    A0);
        sh_pu0[i] = fmaf(rf, purD,  pu00D);
    }
    __syncthreads();

    // window constraints (linear half-planes in (r,c)):
    //  col > j-1 : alpha_m(r) + beta_m*c > 0 ;  col < j+1 : alpha_p(r) + beta_p*c < 0
    const float jf = (float)j;
    const float jm = jf - 1.0f, jp = jf + 1.0f;
    const float bm = Bc - jm * dnc;
    const float bp = Bc - jp * dnc;
    const float rBm = __frcp_rn(bm);
    const float rBp = __frcp_rn(bp);
    const bool  m_lower = (bm > 0.0f);
    const bool  p_lower = (bp < 0.0f);

    // analytic row range (superset; per-row check kept as safety net)
    const float am0 = A0 - jm * dn00, amr = Ar - jm * dnr;
    const float ap0 = A0 - jp * dn00, apr = Ar - jp * dnr;
    const float Km  = fmaxf(0.0f, bm * (float)(IMG_C - 1));
    const float Kp  = fminf(0.0f, bp * (float)(IMG_C - 1));
    float rlo_f = 0.0f, rhi_f = (float)(IMG_R - 1);
    bool empty = false;
    {   // exists c: am0+Km + amr*r > 0
        const float s = am0 + Km;
        if (amr > 0.0f)       rlo_f = fmaxf(rlo_f, __fdividef(-s, amr));
        else if (amr < 0.0f)  rhi_f = fminf(rhi_f, __fdividef(-s, amr));
        else if (!(s > 0.0f)) empty = true;
    }
    {   // exists c: ap0+Kp + apr*r < 0
        const float s = ap0 + Kp;
        if (apr < 0.0f)       rlo_f = fmaxf(rlo_f, __fdividef(-s, apr));
        else if (apr > 0.0f)  rhi_f = fminf(rhi_f, __fdividef(-s, apr));
        else if (!(s < 0.0f)) empty = true;
    }
    int r0 = 0, r1 = -1;
    if (!empty && rhi_f >= rlo_f) {
        r0 = max(0, (int)floorf(rlo_f) - 1);
        r1 = min(IMG_R - 1, (int)ceilf(rhi_f) + 1);
    }

    float acc = 0.0f;
    const float* rowBase = img + r0 * IMG_C;

    for (int r = r0; r <= r1; ++r, rowBase += IMG_C) {
        const float dn0 = sh_dn0[r];
        const float AD  = sh_AD[r];

        const float cm = fmaf(jm, dn0, -AD) * rBm;   // c-bound from col>j-1
        const float cp = fmaf(jp, dn0, -AD) * rBp;   // c-bound from col<j+1
        float lo = 0.0f, hi = (float)(IMG_C - 1);
        if (m_lower) lo = fmaxf(lo, cm); else hi = fminf(hi, cm);
        if (p_lower) lo = fmaxf(lo, cp); else hi = fminf(hi, cp);
        if (hi < lo) continue;

        const int ilo = max(0, (int)ceilf(lo - 0.02f));
        const int ihi = min(IMG_C - 1, (int)floorf(hi + 0.02f));
        if (ihi < ilo) continue;

        const float cf0 = (float)ilo;
        float den = fmaf(cf0, dnc,  dn0);
        float puD = fmaf(cf0, pucD, sh_pu0[r]);

        for (int c = ilo; c <= ihi; ++c) {
            const float t   = __fdividef(nu, den);
            const float col = fmaf(t, puD, su0D);
            const float w   = 1.0f - fabsf(col - jf);
            if (w > 0.0f)
                acc = fmaf(w, rowBase[c], acc);
            den += dnc;
            puD += pucD;
        }
    }

    out[v * N_COLS + j] = acc;
}

extern "C" void kernel_launch(void* const* d_in, const int* in_sizes, int n_in,
                              void* d_out, int out_size) {
    const float* img    = (const float*)d_in[0];
    const float* src    = (const float*)d_in[1];
    const float* detc   = (const float*)d_in[2];
    const float* u      = (const float*)d_in[3];
    const float* center = (const float*)d_in[4];
    const float* cdir   = (const float*)d_in[5];
    float* out = (float*)d_out;

    dim3 grid(3, N_VIEWS);
    fanbeam_gather_kernel<<<grid, 256>>>(img, src, detc, u, center, cdir, out);
}